// round 15
// baseline (speedup 1.0000x reference)
#include <cuda_runtime.h>

#define TPB 128
typedef unsigned long long ull;

// MULT = pi - float-eps, folded into the stage-E form.
#define MULT_F (3.141592653589793 - 1.1920928955078125e-07)

// Precomputed bilinear-form tensor, packed f32x2, contiguous:
//   [c*200 + a*10 + b]        : circuits 0..11 (stages A,B,C), (N_q0, N_q1)
//   [c*200 + 100 + a*10 + b]  : circuits 0..11, (N_q2, N_q3)
//   [2400 + d*100 + a*10 + b] : stage-D circuits d=0..3, (N, N) duplicated
//   [2800 + a*10 + b]         : stage-E form, (N*MULT, N*MULT)
__device__ __align__(16) ull g_N[2900];

// theta slice per circuit: A->theta[0], B->theta[3], C->theta[4], D->theta[1], E->theta[2][0]
__device__ __forceinline__ int circ_slice(int c) {
    if (c < 4)  return c;
    if (c < 8)  return 12 + (c - 4);
    if (c < 12) return 16 + (c - 8);
    if (c < 16) return 4 + (c - 12);
    return 8;
}

__device__ __forceinline__ ull pk2(float lo, float hi) {
    ull r; asm("mov.b64 %0, {%1, %2};" : "=l"(r) : "f"(lo), "f"(hi)); return r;
}
__device__ __forceinline__ void unpk2(ull v, float& lo, float& hi) {
    asm("mov.b64 {%0, %1}, %2;" : "=f"(lo), "=f"(hi) : "l"(v));
}
__device__ __forceinline__ ull ffma2(ull a, ull b, ull c) {
    ull d; asm("fma.rn.f32x2 %0, %1, %2, %3;" : "=l"(d) : "l"(a), "l"(b), "l"(c)); return d;
}
__device__ __forceinline__ ull fmul2(ull a, ull b) {
    ull d; asm("mul.rn.f32x2 %0, %1, %2;" : "=l"(d) : "l"(a), "l"(b)); return d;
}
__device__ __forceinline__ ull fadd2(ull a, ull b) {
    ull d; asm("add.rn.f32x2 %0, %1, %2;" : "=l"(d) : "l"(a), "l"(b)); return d;
}

// ---------------------------------------------------------------------------
// Build kernel: one block per circuit (grid 17, block 100).
// Threads 0..15 build the 16x16 unitary columns; then 100 threads compute the
// symmetrized bilinear tensor N[a][b] (a,b index unordered pairs, i<=i').
// ---------------------------------------------------------------------------
__global__ void build_WM(const float* __restrict__ theta) {
    const int c = blockIdx.x, t = threadIdx.x;
    __shared__ float sWr[16][16], sWi[16][16];   // [k][col]

    if (t < 16) {
        const int col = t;
        const float* w = theta + circ_slice(c) * 48;
        float sr[16], si[16];
#pragma unroll
        for (int i = 0; i < 16; i++) { sr[i] = (i == col) ? 1.f : 0.f; si[i] = 0.f; }
#pragma unroll
        for (int l = 0; l < 4; l++) {
#pragma unroll
            for (int q = 0; q < 4; q++) {
                const float phi = w[(l * 4 + q) * 3 + 0];
                const float th  = w[(l * 4 + q) * 3 + 1];
                const float om  = w[(l * 4 + q) * 3 + 2];
                float ch, sh, ca, sa, cb, sb;
                __sincosf(0.5f * th, &sh, &ch);
                __sincosf(0.5f * (phi + om), &sa, &ca);
                __sincosf(0.5f * (phi - om), &sb, &cb);
                const float u00r =  ca * ch, u00i = -sa * ch;
                const float u01r = -cb * sh, u01i = -sb * sh;
                const float u10r =  cb * sh, u10i = -sb * sh;
                const float u11r =  ca * ch, u11i =  sa * ch;
                const int mask = 8 >> q;
#pragma unroll
                for (int k = 0; k < 16; k++) {
                    if (k & mask) continue;
                    const int k1 = k | mask;
                    float ar = sr[k],  ai = si[k];
                    float br = sr[k1], bi = si[k1];
                    sr[k]  = u00r * ar - u00i * ai + u01r * br - u01i * bi;
                    si[k]  = u00r * ai + u00i * ar + u01r * bi + u01i * br;
                    sr[k1] = u10r * ar - u10i * ai + u11r * br - u11i * bi;
                    si[k1] = u10r * ai + u10i * ar + u11r * bi + u11i * br;
                }
            }
            const int r = (l % 3) + 1;
#pragma unroll
            for (int q = 0; q < 4; q++) {
                const int cm = 8 >> q;
                const int tm = 8 >> ((q + r) & 3);
#pragma unroll
                for (int k = 0; k < 16; k++) {
                    if ((k & cm) && !(k & tm)) {
                        const int k1 = k | tm;
                        float tr = sr[k], ti = si[k];
                        sr[k] = sr[k1]; si[k] = si[k1];
                        sr[k1] = tr;    si[k1] = ti;
                    }
                }
            }
        }
#pragma unroll
        for (int k = 0; k < 16; k++) { sWr[k][col] = sr[k]; sWi[k][col] = si[k]; }
    }
    __syncthreads();

    // N tensor: thread t -> (a, b). Sum over index orderings and k.
    const int PI[10] = {0,0,0,0,1,1,1,2,2,3};
    const int PJ[10] = {0,1,2,3,1,2,3,2,3,3};
    const int a = t / 10, b = t % 10;   // t < 100
    const int i0 = PI[a], i1 = PJ[a], j0 = PI[b], j1 = PJ[b];
    const int na = (i0 == i1) ? 1 : 2;
    const int nb = (j0 == j1) ? 1 : 2;

    float n0 = 0.f, n1 = 0.f, n2 = 0.f, n3 = 0.f;
    for (int ai = 0; ai < na; ai++) {
        const int A0 = ai ? i1 : i0, A1 = ai ? i0 : i1;
        for (int bi = 0; bi < nb; bi++) {
            const int B0 = bi ? j1 : j0, B1 = bi ? j0 : j1;
            const int r  = 4 * A0 + B0;
            const int cc = 4 * A1 + B1;
#pragma unroll
            for (int k = 0; k < 16; k++) {
                const float tt = sWr[k][r] * sWr[k][cc] + sWi[k][r] * sWi[k][cc];
                n0 += (k & 8) ? -tt : tt;
                n1 += (k & 4) ? -tt : tt;
                n2 += (k & 2) ? -tt : tt;
                n3 += (k & 1) ? -tt : tt;
            }
        }
    }

    const int idx = a * 10 + b;
    if (c < 12) {
        g_N[c * 200 + idx]       = pk2(n0, n1);
        g_N[c * 200 + 100 + idx] = pk2(n2, n3);
    } else if (c < 16) {
        g_N[2400 + (c - 12) * 100 + idx] = pk2(n0, n0);
    } else {
        const float ns = n0 * (float)MULT_F;
        g_N[2800 + idx] = pk2(ns, ns);
    }
    // PDL: allow the dependent (main) kernel to start scheduling.
    asm volatile("griddepcontrol.launch_dependents;" ::: "memory");
}

// ---------------------------------------------------------------------------
// Per-circuit evaluation via bilinear forms.
// pA kept SCALAR (packed per-use in the t-loop) to shorten register liveness.
// ---------------------------------------------------------------------------
__device__ __forceinline__ void make_pq(const float* a, float* pA, ull* qBp) {
    float s0, c0, s1, c1, s2, c2, s3, c3;
    __sincosf(0.5f * a[0], &s0, &c0);
    __sincosf(0.5f * a[1], &s1, &c1);
    __sincosf(0.5f * a[2], &s2, &c2);
    __sincosf(0.5f * a[3], &s3, &c3);
    const float u0 = c0 * c1, u1 = c0 * s1, u2 = s0 * c1, u3 = s0 * s1;
    const float v0 = c2 * c3, v1 = c2 * s3, v2 = s2 * c3, v3 = s2 * s3;
    pA[0] = u0*u0; pA[1] = u0*u1; pA[2] = u0*u2; pA[3] = u0*u3; pA[4] = u1*u1;
    pA[5] = u1*u2; pA[6] = u1*u3; pA[7] = u2*u2; pA[8] = u2*u3; pA[9] = u3*u3;
    const float qB[10] = { v0*v0, v0*v1, v0*v2, v0*v3, v1*v1,
                           v1*v2, v1*v3, v2*v2, v2*v3, v3*v3 };
#pragma unroll
    for (int i = 0; i < 10; i++) qBp[i] = pk2(qB[i], qB[i]);
}

// 4 expvals: forms (q0,q1) at N[0..99], (q2,q3) at N[100..199], packed.
__device__ __forceinline__ void runQ4(const ull* __restrict__ N, const float* a, float* o) {
    float pA[10]; ull qBp[10];
    make_pq(a, pA, qBp);
    ull e01 = 0ull, e23 = 0ull;
#pragma unroll
    for (int t = 0; t < 10; t++) {
        const ull pAt = pk2(pA[t], pA[t]);
        const ulonglong2* r01 = (const ulonglong2*)(N + t * 10);
        const ulonglong2* r23 = (const ulonglong2*)(N + 100 + t * 10);
        ull t0 = fmul2(r01[0].x, qBp[0]), t1 = fmul2(r01[0].y, qBp[1]);
        t0 = ffma2(r01[1].x, qBp[2], t0); t1 = ffma2(r01[1].y, qBp[3], t1);
        t0 = ffma2(r01[2].x, qBp[4], t0); t1 = ffma2(r01[2].y, qBp[5], t1);
        t0 = ffma2(r01[3].x, qBp[6], t0); t1 = ffma2(r01[3].y, qBp[7], t1);
        t0 = ffma2(r01[4].x, qBp[8], t0); t1 = ffma2(r01[4].y, qBp[9], t1);
        e01 = ffma2(pAt, fadd2(t0, t1), e01);
        ull s0 = fmul2(r23[0].x, qBp[0]), s1 = fmul2(r23[0].y, qBp[1]);
        s0 = ffma2(r23[1].x, qBp[2], s0); s1 = ffma2(r23[1].y, qBp[3], s1);
        s0 = ffma2(r23[2].x, qBp[4], s0); s1 = ffma2(r23[2].y, qBp[5], s1);
        s0 = ffma2(r23[3].x, qBp[6], s0); s1 = ffma2(r23[3].y, qBp[7], s1);
        s0 = ffma2(r23[4].x, qBp[8], s0); s1 = ffma2(r23[4].y, qBp[9], s1);
        e23 = ffma2(pAt, fadd2(s0, s1), e23);
    }
    float lo, hi;
    unpk2(e01, lo, hi); o[0] = lo; o[1] = hi;
    unpk2(e23, lo, hi); o[2] = lo; o[3] = hi;
}

// Single expval (duplicated-packed form at N[0..99]).
__device__ __forceinline__ float runQ1(const ull* __restrict__ N, const float* a) {
    float pA[10]; ull qBp[10];
    make_pq(a, pA, qBp);
    ull e = 0ull;
#pragma unroll
    for (int t = 0; t < 10; t++) {
        const ull pAt = pk2(pA[t], pA[t]);
        const ulonglong2* r = (const ulonglong2*)(N + t * 10);
        ull t0 = fmul2(r[0].x, qBp[0]), t1 = fmul2(r[0].y, qBp[1]);
        t0 = ffma2(r[1].x, qBp[2], t0); t1 = ffma2(r[1].y, qBp[3], t1);
        t0 = ffma2(r[2].x, qBp[4], t0); t1 = ffma2(r[2].y, qBp[5], t1);
        t0 = ffma2(r[3].x, qBp[6], t0); t1 = ffma2(r[3].y, qBp[7], t1);
        t0 = ffma2(r[4].x, qBp[8], t0); t1 = ffma2(r[4].y, qBp[9], t1);
        e = ffma2(pAt, fadd2(t0, t1), e);
    }
    float lo, hi; unpk2(e, lo, hi);
    return lo;
}

// ---------------------------------------------------------------------------
// Main kernel: block = 32-element tile, warp w = circuit w of each stage,
// lane = element. All N reads are full-warp broadcasts. 8 blocks/SM target.
// ---------------------------------------------------------------------------
__global__ __launch_bounds__(TPB, 8)
void vqc_warp(const float* __restrict__ x, float* __restrict__ out, int B) {
    __shared__ __align__(16) ull sN[2900];     // 23.2 KB
    __shared__ float sH[32][17];               // 2.1 KB, stride-17 pad

    const int tid = threadIdx.x;

    // x tile load first — overlaps with the (PDL) primary kernel still running.
    const int e0 = blockIdx.x * 32;
    for (int i = tid; i < 32 * 13; i += TPB) {
        const long gi = (long)e0 * 13 + i;
        if (gi < (long)B * 13) sH[i / 13][i % 13] = x[gi];
    }

    asm volatile("griddepcontrol.wait;" ::: "memory");
    {
        const float4* s1 = (const float4*)g_N;
        float4* d1 = (float4*)sN;
        for (int i = tid; i < 1450; i += TPB) d1[i] = s1[i];
    }
    __syncthreads();

    const int w = tid >> 5;   // warp = circuit index within stage
    const int e = tid & 31;   // lane  = element within tile
    float a[4], o[4];

    // Stage A angles: H = [0, x0..x12, 0, 0]; circuit w uses H[4w..4w+3]
#pragma unroll
    for (int i = 0; i < 4; i++) {
        const int j = 4 * w + i;
        a[i] = (j >= 1 && j <= 13) ? sH[e][j - 1] : 0.f;
    }
    __syncthreads();

    // Stage A
    runQ4(sN + w * 200, a, o);
#pragma unroll
    for (int i = 0; i < 4; i++) sH[e][4 * w + i] = o[i];
    __syncthreads();
#pragma unroll
    for (int i = 0; i < 4; i++) a[i] = sH[e][4 * i + w];    // transposed wiring
    __syncthreads();

    // Stage B
    runQ4(sN + (4 + w) * 200, a, o);
#pragma unroll
    for (int i = 0; i < 4; i++) sH[e][4 * w + i] = o[i];
    __syncthreads();
#pragma unroll
    for (int i = 0; i < 4; i++) a[i] = sH[e][4 * i + w];
    __syncthreads();

    // Stage C
    runQ4(sN + (8 + w) * 200, a, o);
#pragma unroll
    for (int i = 0; i < 4; i++) sH[e][4 * w + i] = o[i];
    __syncthreads();
#pragma unroll
    for (int i = 0; i < 4; i++) a[i] = sH[e][4 * i + w];
    __syncthreads();

    // Stage D: form w
    const float h4 = runQ1(sN + 2400 + w * 100, a);
    sH[e][w] = h4;
    __syncthreads();

    // Stage E: warp 0 only (MULT baked into the E form); warp-uniform branch
    if (w != 0) return;
#pragma unroll
    for (int i = 0; i < 4; i++) a[i] = sH[e][i];
    const float r = runQ1(sN + 2800, a);
    if (e0 + e < B) out[e0 + e] = r;
}

extern "C" void kernel_launch(void* const* d_in, const int* in_sizes, int n_in,
                              void* d_out, int out_size) {
    const float* x     = (const float*)d_in[0];
    const float* theta = (const float*)d_in[1];
    if (n_in >= 2 && in_sizes[0] < in_sizes[1]) {
        x     = (const float*)d_in[1];
        theta = (const float*)d_in[0];
    }
    float* out = (float*)d_out;
    const int B = out_size;

    build_WM<<<17, 100>>>(theta);

    // Secondary launch with programmatic dependent launch (overlaps with build).
    cudaLaunchConfig_t cfg = {};
    cfg.gridDim  = dim3((B + 31) / 32);
    cfg.blockDim = dim3(TPB);
    cfg.dynamicSmemBytes = 0;
    cfg.stream = 0;
    cudaLaunchAttribute attrs[1];
    attrs[0].id = cudaLaunchAttributeProgrammaticStreamSerialization;
    attrs[0].val.programmaticStreamSerializationAllowed = 1;
    cfg.attrs = attrs;
    cfg.numAttrs = 1;
    cudaLaunchKernelEx(&cfg, vqc_warp, x, out, B);
}